// round 1
// baseline (speedup 1.0000x reference)
#include <cuda_runtime.h>
#include <math.h>

#define BB 32
#define AA 1024
#define FF 128
#define NN (BB*AA)
#define MT 64

// ---------------- scratch (no allocations allowed) ----------------
__device__ float g_u2[2][FF];     // W_lin @ k_{plus,minus}
__device__ float g_bk2[2];        // b_lin . k_{plus,minus}
__device__ float g_wow[FF];       // Wout @ w_e
__device__ float g_acoef[NN];     // per-atom attention coefficient a
__device__ float g_ezwe[NN];      // e_z . w_e per row
__device__ float g_pred[NN];      // predicted charge (pre-correction)
__device__ float g_qatom[NN];     // corrected charge
__device__ float g_partial[BB*8]; // pair-energy partials

__device__ __forceinline__ float siluf(float x){ return x / (1.0f + expf(-x)); }

// ---------------- K0: tiny precompute ----------------
__global__ void k0_prep(const float* __restrict__ W_lin, const float* __restrict__ b_lin,
                        const float* __restrict__ kp, const float* __restrict__ km,
                        const float* __restrict__ Wout, const float* __restrict__ w_e) {
    int g = threadIdx.x; // 0..127
    float up = 0.f, um = 0.f, wo = 0.f;
    #pragma unroll 4
    for (int f = 0; f < FF; f++) {
        float w = W_lin[g*FF + f];
        up += w * kp[f];
        um += w * km[f];
        wo += Wout[g*FF + f] * w_e[f];
    }
    g_u2[0][g] = up; g_u2[1][g] = um; g_wow[g] = wo;
    if (g == 0) {
        float bp = 0.f, bm = 0.f;
        for (int f = 0; f < FF; f++) { bp += b_lin[f]*kp[f]; bm += b_lin[f]*km[f]; }
        g_bk2[0] = bp; g_bk2[1] = bm;
    }
}

// ---------------- K1: attention coefficients + e_z.w_e ----------------
__global__ void k1_acoef(const float* __restrict__ e_z, const float* __restrict__ charge) {
    int b = blockIdx.x;
    int tid = threadIdx.x;
    __shared__ float s_u[FF];
    __shared__ float s_we_unused; (void)s_we_unused;
    __shared__ float s_we[FF];
    __shared__ float s_num[AA];
    __shared__ float s_red[256];

    float c = charge[b];
    int sgn = (c >= 0.0f) ? 0 : 1;
    if (tid < FF) { s_u[tid] = g_u2[sgn][tid]; }
    __syncthreads();

    float bk = g_bk2[sgn];
    const float inv_sqrtF = 0.08838834764831845f; // 1/sqrt(128)
    float mysum = 0.f;
    #pragma unroll
    for (int it = 0; it < 4; it++) {
        int a = tid + it*256;
        size_t n = (size_t)b*AA + a;
        const float4* ez = (const float4*)(e_z + n*FF);
        float d1 = 0.f;
        #pragma unroll
        for (int f4 = 0; f4 < 32; f4++) {
            float4 v = ez[f4];
            int f = f4*4;
            d1 += v.x*s_u[f] + v.y*s_u[f+1] + v.z*s_u[f+2] + v.w*s_u[f+3];
        }
        float arg = (d1 + bk) * inv_sqrtF;
        float num = fmaxf(arg, 0.f) + log1pf(expf(-fabsf(arg)));
        s_num[a] = num;
        mysum += num;
    }
    s_red[tid] = mysum;
    __syncthreads();
    for (int off = 128; off > 0; off >>= 1) {
        if (tid < off) s_red[tid] += s_red[tid + off];
        __syncthreads();
    }
    float total = s_red[0];
    #pragma unroll
    for (int it = 0; it < 4; it++) {
        int a = tid + it*256;
        g_acoef[b*AA + a] = c * s_num[a] / total;
    }
}

// ---------------- K1b: e_z . w_e per row ----------------
__global__ void k1b_ezwe(const float* __restrict__ e_z, const float* __restrict__ w_e) {
    __shared__ float s_we[FF];
    int tid = threadIdx.x;
    if (tid < FF) s_we[tid] = w_e[tid];
    __syncthreads();
    size_t n = (size_t)blockIdx.x * 256 + tid; // NN/256 = 128 blocks
    const float4* ez = (const float4*)(e_z + n*FF);
    float d2 = 0.f;
    #pragma unroll
    for (int f4 = 0; f4 < 32; f4++) {
        float4 v = ez[f4];
        int f = f4*4;
        d2 += v.x*s_we[f] + v.y*s_we[f+1] + v.z*s_we[f+2] + v.w*s_we[f+3];
    }
    g_ezwe[n] = d2;
}

// ---------------- K2: fused res-MLP (2 GEMMs + folded Wout dot) ----------------
// dyn smem: sW1[128*128] sW2[128*128] sX[64*132] s_a[64] s_v[128] s_wow[128]
__global__ void __launch_bounds__(256, 1)
k2_mlp(const float* __restrict__ Wr1, const float* __restrict__ Wr2,
       const float* __restrict__ vp, const float* __restrict__ vm,
       const float* __restrict__ charge, const int* __restrict__ z,
       const float* __restrict__ q_tab) {
    extern __shared__ float smem[];
    float* sW1  = smem;             // 16384 floats
    float* sW2  = sW1 + FF*FF;      // 16384
    float* sX   = sW2 + FF*FF;      // 64*132 = 8448 (padded rows: stride 132)
    float* s_a  = sX + MT*132;      // 64
    float* s_v  = s_a + MT;         // 128
    float* s_wow= s_v + FF;         // 128

    int tid = threadIdx.x;
    int m0 = blockIdx.x * MT;       // tile of 64 rows, single molecule per tile
    int b = m0 >> 10;
    const float* v = (charge[b] >= 0.f) ? vp : vm;

    const float4* W1v = (const float4*)Wr1;
    const float4* W2v = (const float4*)Wr2;
    float4* sW1v = (float4*)sW1;
    float4* sW2v = (float4*)sW2;
    #pragma unroll
    for (int i = tid; i < FF*FF/4; i += 256) { sW1v[i] = W1v[i]; sW2v[i] = W2v[i]; }
    if (tid < FF) { s_v[tid] = v[tid]; s_wow[tid] = g_wow[tid]; }
    if (tid < MT) s_a[tid] = g_acoef[m0 + tid];
    __syncthreads();

    // sX = silu(a * v)
    for (int i = tid; i < MT*FF; i += 256) {
        int m = i >> 7, k = i & 127;
        sX[m*132 + k] = siluf(s_a[m] * s_v[k]);
    }
    __syncthreads();

    int w = tid >> 5, lane = tid & 31;
    int r0 = w * 8;        // 8 rows per warp-group
    int c0 = lane * 4;     // 4 cols per lane

    float acc[8][4];
    // ---- GEMM1: h1 = sX @ Wr1 ----
    #pragma unroll
    for (int r = 0; r < 8; r++)
        #pragma unroll
        for (int c = 0; c < 4; c++) acc[r][c] = 0.f;
    #pragma unroll 8
    for (int k = 0; k < FF; k++) {
        float4 wv = *(const float4*)&sW1[k*FF + c0];
        #pragma unroll
        for (int r = 0; r < 8; r++) {
            float a = sX[(r0 + r)*132 + k];
            acc[r][0] += a*wv.x; acc[r][1] += a*wv.y;
            acc[r][2] += a*wv.z; acc[r][3] += a*wv.w;
        }
    }
    __syncthreads();
    // overwrite sX with silu(h1)
    #pragma unroll
    for (int r = 0; r < 8; r++)
        #pragma unroll
        for (int c = 0; c < 4; c++)
            sX[(r0 + r)*132 + c0 + c] = siluf(acc[r][c]);
    __syncthreads();

    // ---- GEMM2: h2 = silu(h1) @ Wr2 ----
    #pragma unroll
    for (int r = 0; r < 8; r++)
        #pragma unroll
        for (int c = 0; c < 4; c++) acc[r][c] = 0.f;
    #pragma unroll 8
    for (int k = 0; k < FF; k++) {
        float4 wv = *(const float4*)&sW2[k*FF + c0];
        #pragma unroll
        for (int r = 0; r < 8; r++) {
            float a = sX[(r0 + r)*132 + k];
            acc[r][0] += a*wv.x; acc[r][1] += a*wv.y;
            acc[r][2] += a*wv.z; acc[r][3] += a*wv.w;
        }
    }

    // ---- epilogue: s = silu(x + h2) . (Wout @ w_e);  pred_q = ezwe + s + tab[z]
    float vv[4], ww[4];
    #pragma unroll
    for (int c = 0; c < 4; c++) { vv[c] = s_v[c0 + c]; ww[c] = s_wow[c0 + c]; }
    #pragma unroll
    for (int r = 0; r < 8; r++) {
        float am = s_a[r0 + r];
        float p = 0.f;
        #pragma unroll
        for (int c = 0; c < 4; c++)
            p += siluf(am*vv[c] + acc[r][c]) * ww[c];
        #pragma unroll
        for (int off = 16; off > 0; off >>= 1)
            p += __shfl_down_sync(0xffffffffu, p, off);
        if (lane == 0) {
            int n = m0 + r0 + r;
            g_pred[n] = g_ezwe[n] + p + q_tab[z[n]];
        }
    }
}

// ---------------- K3: charge-conserving correction ----------------
__global__ void k3_correct(const float* __restrict__ charge) {
    int b = blockIdx.x; int tid = threadIdx.x;
    __shared__ float s_red[256];
    float s = 0.f;
    #pragma unroll
    for (int it = 0; it < 4; it++) s += g_pred[b*AA + tid + it*256];
    s_red[tid] = s; __syncthreads();
    for (int off = 128; off > 0; off >>= 1) {
        if (tid < off) s_red[tid] += s_red[tid + off];
        __syncthreads();
    }
    float corr = (charge[b] - s_red[0]) * (1.0f / AA);
    #pragma unroll
    for (int it = 0; it < 4; it++) {
        int n = b*AA + tid + it*256;
        g_qatom[n] = g_pred[n] + corr;
    }
}

// ---------------- K4: O(A^2) switched Coulomb ----------------
__global__ void k4_pair(const float* __restrict__ xyz) {
    int b = blockIdx.y; int t = blockIdx.x; int tid = threadIdx.x;
    __shared__ float sx[AA], sy[AA], sz[AA], sq[AA];
    __shared__ float s_red[256];
    for (int a = tid; a < AA; a += 256) {
        size_t base = ((size_t)b*AA + a) * 3;
        sx[a] = xyz[base]; sy[a] = xyz[base+1]; sz[a] = xyz[base+2];
        sq[a] = g_qatom[b*AA + a];
    }
    __syncthreads();

    const float RON = 1.25f, INVW = 0.4f;           // 1/(R_OFF-R_ON)
    const float RON2 = 1.5625f, ROFF2 = 14.0625f;   // 1.25^2, 3.75^2
    float e = 0.f;
    int i0 = t * 128;
    for (int idx = tid; idx < 128*1024; idx += 256) {
        int il = idx >> 10; int j = idx & 1023;
        int i = i0 + il;
        if (j > i) {
            float dx = sx[i]-sx[j], dy = sy[i]-sy[j], dz = sz[i]-sz[j];
            float r2 = dx*dx + dy*dy + dz*dz;
            float qq = sq[i] * sq[j];
            float coul;
            if (r2 >= ROFF2) {
                coul = rsqrtf(r2);                       // fs = 0 exactly
            } else if (r2 <= RON2) {
                coul = rsqrtf(r2 + 1.f);                 // fs = 1 exactly
            } else {
                float r = sqrtf(r2);
                float arg = (r - RON) * INVW;            // in (0,1)
                float num = expf(-1.f / (1.f - arg));
                float den = expf(-1.f / arg);
                float fs = num / (num + den);
                coul = fs * rsqrtf(r2 + 1.f) + (1.f - fs) / r;
            }
            e += qq * coul;
        }
    }
    s_red[tid] = e; __syncthreads();
    for (int off = 128; off > 0; off >>= 1) {
        if (tid < off) s_red[tid] += s_red[tid + off];
        __syncthreads();
    }
    if (tid == 0) g_partial[b*8 + t] = s_red[0];
}

// ---------------- K5: finalize ----------------
__global__ void k5_final(float* __restrict__ out) {
    int b = threadIdx.x;
    if (b < BB) {
        float s = 0.f;
        #pragma unroll
        for (int t = 0; t < 8; t++) s += g_partial[b*8 + t];
        out[b] = 332.0636f * s;
    }
}

extern "C" void kernel_launch(void* const* d_in, const int* in_sizes, int n_in,
                              void* d_out, int out_size) {
    const float* e_z     = (const float*)d_in[0];
    const float* charge  = (const float*)d_in[1];
    const float* xyz     = (const float*)d_in[2];
    const float* W_lin   = (const float*)d_in[3];
    const float* b_lin   = (const float*)d_in[4];
    const float* k_plus  = (const float*)d_in[5];
    const float* k_minus = (const float*)d_in[6];
    const float* v_plus  = (const float*)d_in[7];
    const float* v_minus = (const float*)d_in[8];
    const float* Wr1     = (const float*)d_in[9];
    const float* Wr2     = (const float*)d_in[10];
    const float* Wout    = (const float*)d_in[11];
    const float* w_e     = (const float*)d_in[12];
    const float* q_tab   = (const float*)d_in[13];
    const int*   z       = (const int*)d_in[14];
    float* out = (float*)d_out;

    const int smem_k2 = (FF*FF*2 + MT*132 + MT + FF + FF) * (int)sizeof(float); // 166144
    cudaFuncSetAttribute(k2_mlp, cudaFuncAttributeMaxDynamicSharedMemorySize, smem_k2);

    k0_prep<<<1, 128>>>(W_lin, b_lin, k_plus, k_minus, Wout, w_e);
    k1_acoef<<<BB, 256>>>(e_z, charge);
    k1b_ezwe<<<NN/256, 256>>>(e_z, w_e);
    k2_mlp<<<NN/MT, 256, smem_k2>>>(Wr1, Wr2, v_plus, v_minus, charge, z, q_tab);
    k3_correct<<<BB, 256>>>(charge);
    dim3 g4(8, BB);
    k4_pair<<<g4, 256>>>(xyz);
    k5_final<<<1, 32>>>(out);
}

// round 2
// speedup vs baseline: 1.4473x; 1.4473x over previous
#include <cuda_runtime.h>
#include <math.h>

#define BB 32
#define AA 1024
#define FF 128
#define NN (BB*AA)
#define MT 128   // rows per k2 block

// ---------------- scratch (no allocations allowed) ----------------
__device__ float g_u2[2][FF];       // W_lin @ k_{plus,minus}
__device__ float g_bk2[2];          // b_lin . k_{plus,minus}
__device__ float g_wow[FF];         // Wout @ w_e
__device__ float g_num[NN];         // softplus(arg) per atom
__device__ float g_numpart[NN/256]; // per-block partial sums of num (4 per molecule)
__device__ float g_ezwe[NN];        // e_z . w_e per row
__device__ float g_pred[NN];        // predicted charge (pre-correction)
__device__ float g_qatom[NN];       // corrected charge
__device__ float g_partial[BB*8];   // pair-energy partials

__device__ __forceinline__ float siluf(float x){ return x / (1.0f + expf(-x)); }

// ---------------- K0: tiny precompute ----------------
__global__ void k0_prep(const float* __restrict__ W_lin, const float* __restrict__ b_lin,
                        const float* __restrict__ kp, const float* __restrict__ km,
                        const float* __restrict__ Wout, const float* __restrict__ w_e) {
    int g = threadIdx.x; // 0..127
    float up = 0.f, um = 0.f, wo = 0.f;
    #pragma unroll 4
    for (int f = 0; f < FF; f++) {
        float w = W_lin[g*FF + f];
        up += w * kp[f];
        um += w * km[f];
        wo += Wout[g*FF + f] * w_e[f];
    }
    g_u2[0][g] = up; g_u2[1][g] = um; g_wow[g] = wo;
    if (g == 0) {
        float bp = 0.f, bm = 0.f;
        for (int f = 0; f < FF; f++) { bp += b_lin[f]*kp[f]; bm += b_lin[f]*km[f]; }
        g_bk2[0] = bp; g_bk2[1] = bm;
    }
}

// ---------------- K1: fused row dots (e_z.u_sgn and e_z.w_e), one pass over e_z ----
// 128 blocks x 256 threads, one row per thread. Rows of a block lie in ONE molecule.
__global__ void k1_fused(const float* __restrict__ e_z, const float* __restrict__ charge,
                         const float* __restrict__ w_e) {
    __shared__ float s_u[FF];
    __shared__ float s_we[FF];
    __shared__ float s_red[256];
    int bb = blockIdx.x;            // 0..127
    int b  = bb >> 2;               // molecule (4 blocks per molecule)
    int tid = threadIdx.x;
    float c = charge[b];
    int sgn = (c >= 0.0f) ? 0 : 1;
    if (tid < FF) { s_u[tid] = g_u2[sgn][tid]; s_we[tid] = w_e[tid]; }
    __syncthreads();

    size_t n = (size_t)bb * 256 + tid;
    const float4* ez = (const float4*)(e_z + n*FF);
    float d1 = 0.f, d2 = 0.f;
    #pragma unroll
    for (int f4 = 0; f4 < 32; f4++) {
        float4 v = ez[f4];
        int f = f4*4;
        d1 += v.x*s_u[f]  + v.y*s_u[f+1]  + v.z*s_u[f+2]  + v.w*s_u[f+3];
        d2 += v.x*s_we[f] + v.y*s_we[f+1] + v.z*s_we[f+2] + v.w*s_we[f+3];
    }
    const float inv_sqrtF = 0.08838834764831845f;
    float arg = (d1 + g_bk2[sgn]) * inv_sqrtF;
    float num = fmaxf(arg, 0.f) + log1pf(expf(-fabsf(arg)));
    g_num[n] = num;
    g_ezwe[n] = d2;

    s_red[tid] = num;
    __syncthreads();
    for (int off = 128; off > 0; off >>= 1) {
        if (tid < off) s_red[tid] += s_red[tid + off];
        __syncthreads();
    }
    if (tid == 0) g_numpart[bb] = s_red[0];
}

// ---------------- K2: fused res-MLP (2 GEMMs + folded Wout dot) ----------------
__global__ void __launch_bounds__(512, 1)
k2_mlp(const float* __restrict__ Wr1, const float* __restrict__ Wr2,
       const float* __restrict__ vp, const float* __restrict__ vm,
       const float* __restrict__ charge, const int* __restrict__ z,
       const float* __restrict__ q_tab) {
    extern __shared__ float smem[];
    float* sW1  = smem;             // 16384 floats
    float* sW2  = sW1 + FF*FF;      // 16384
    float* sX   = sW2 + FF*FF;      // 128*132 (padded rows, stride 132)
    float* s_a  = sX + MT*132;      // 128
    float* s_v  = s_a + MT;         // 128
    float* s_wow= s_v + FF;         // 128

    int tid = threadIdx.x;
    int m0 = blockIdx.x * MT;       // tile of 128 rows, single molecule per tile
    int b = m0 >> 10;
    float c = charge[b];
    const float* v = (c >= 0.f) ? vp : vm;

    const float4* W1v = (const float4*)Wr1;
    const float4* W2v = (const float4*)Wr2;
    float4* sW1v = (float4*)sW1;
    float4* sW2v = (float4*)sW2;
    #pragma unroll
    for (int i = tid; i < FF*FF/4; i += 512) { sW1v[i] = W1v[i]; sW2v[i] = W2v[i]; }
    if (tid < FF) { s_v[tid] = v[tid]; s_wow[tid] = g_wow[tid]; }
    if (tid < MT) {
        float tot = g_numpart[b*4] + g_numpart[b*4+1] + g_numpart[b*4+2] + g_numpart[b*4+3];
        s_a[tid] = c * g_num[m0 + tid] / tot;
    }
    __syncthreads();

    // sX = silu(a * v)
    for (int i = tid; i < MT*FF; i += 512) {
        int m = i >> 7, k = i & 127;
        sX[m*132 + k] = siluf(s_a[m] * s_v[k]);
    }
    __syncthreads();

    int w = tid >> 5, lane = tid & 31;
    int r0 = w * 8;        // 8 rows per warp (16 warps x 8 = 128)
    int c0 = lane * 4;     // 4 cols per lane

    float acc[8][4];
    // ---- GEMM1: h1 = sX @ Wr1 ----
    #pragma unroll
    for (int r = 0; r < 8; r++)
        #pragma unroll
        for (int cc = 0; cc < 4; cc++) acc[r][cc] = 0.f;
    #pragma unroll 8
    for (int k = 0; k < FF; k++) {
        float4 wv = *(const float4*)&sW1[k*FF + c0];
        #pragma unroll
        for (int r = 0; r < 8; r++) {
            float a = sX[(r0 + r)*132 + k];
            acc[r][0] += a*wv.x; acc[r][1] += a*wv.y;
            acc[r][2] += a*wv.z; acc[r][3] += a*wv.w;
        }
    }
    __syncthreads();
    #pragma unroll
    for (int r = 0; r < 8; r++)
        #pragma unroll
        for (int cc = 0; cc < 4; cc++)
            sX[(r0 + r)*132 + c0 + cc] = siluf(acc[r][cc]);
    __syncthreads();

    // ---- GEMM2: h2 = silu(h1) @ Wr2 ----
    #pragma unroll
    for (int r = 0; r < 8; r++)
        #pragma unroll
        for (int cc = 0; cc < 4; cc++) acc[r][cc] = 0.f;
    #pragma unroll 8
    for (int k = 0; k < FF; k++) {
        float4 wv = *(const float4*)&sW2[k*FF + c0];
        #pragma unroll
        for (int r = 0; r < 8; r++) {
            float a = sX[(r0 + r)*132 + k];
            acc[r][0] += a*wv.x; acc[r][1] += a*wv.y;
            acc[r][2] += a*wv.z; acc[r][3] += a*wv.w;
        }
    }

    // ---- epilogue: s = silu(x + h2) . (Wout @ w_e);  pred_q = ezwe + s + tab[z]
    float vv[4], ww[4];
    #pragma unroll
    for (int cc = 0; cc < 4; cc++) { vv[cc] = s_v[c0 + cc]; ww[cc] = s_wow[c0 + cc]; }
    #pragma unroll
    for (int r = 0; r < 8; r++) {
        float am = s_a[r0 + r];
        float p = 0.f;
        #pragma unroll
        for (int cc = 0; cc < 4; cc++)
            p += siluf(am*vv[cc] + acc[r][cc]) * ww[cc];
        #pragma unroll
        for (int off = 16; off > 0; off >>= 1)
            p += __shfl_down_sync(0xffffffffu, p, off);
        if (lane == 0) {
            int n = m0 + r0 + r;
            g_pred[n] = g_ezwe[n] + p + q_tab[z[n]];
        }
    }
}

// ---------------- K3: charge-conserving correction ----------------
__global__ void k3_correct(const float* __restrict__ charge) {
    int b = blockIdx.x; int tid = threadIdx.x;
    __shared__ float s_red[256];
    float s = 0.f;
    #pragma unroll
    for (int it = 0; it < 4; it++) s += g_pred[b*AA + tid + it*256];
    s_red[tid] = s; __syncthreads();
    for (int off = 128; off > 0; off >>= 1) {
        if (tid < off) s_red[tid] += s_red[tid + off];
        __syncthreads();
    }
    float corr = (charge[b] - s_red[0]) * (1.0f / AA);
    #pragma unroll
    for (int it = 0; it < 4; it++) {
        int n = b*AA + tid + it*256;
        g_qatom[n] = g_pred[n] + corr;
    }
}

// ---------------- K4: O(A^2) switched Coulomb, bow-tie balanced triangular ----
__device__ __forceinline__ float pair_coul(float r2) {
    const float RON = 1.25f, INVW = 0.4f;           // 1/(R_OFF-R_ON)
    const float RON2 = 1.5625f, ROFF2 = 14.0625f;   // 1.25^2, 3.75^2
    if (r2 >= ROFF2) return rsqrtf(r2);             // fs = 0 exactly
    if (r2 <= RON2)  return rsqrtf(r2 + 1.f);       // fs = 1 exactly
    float r = sqrtf(r2);
    float arg = (r - RON) * INVW;                   // in (0,1)
    float num = expf(-1.f / (1.f - arg));
    float den = expf(-1.f / arg);
    float fs = num / (num + den);
    return fs * rsqrtf(r2 + 1.f) + (1.f - fs) / r;
}

__global__ void k4_pair(const float* __restrict__ xyz) {
    int b = blockIdx.y; int t = blockIdx.x; int tid = threadIdx.x;
    __shared__ float sx[AA], sy[AA], sz[AA], sq[AA];
    __shared__ float s_red[256];
    for (int a = tid; a < AA; a += 256) {
        size_t base = ((size_t)b*AA + a) * 3;
        sx[a] = xyz[base]; sy[a] = xyz[base+1]; sz[a] = xyz[base+2];
        sq[a] = g_qatom[b*AA + a];
    }
    __syncthreads();

    float e = 0.f;
    #pragma unroll 1
    for (int rr = 0; rr < 64; rr++) {
        int i = t*64 + rr;               // i in [0, 512)
        {
            float xi = sx[i], yi = sy[i], zi = sz[i], qi = sq[i];
            for (int j = i + 1 + tid; j < AA; j += 256) {
                float dx = xi - sx[j], dy = yi - sy[j], dz = zi - sz[j];
                float r2 = dx*dx + dy*dy + dz*dz;
                e += qi * sq[j] * pair_coul(r2);
            }
        }
        int i2 = AA - 1 - i;             // mirrored row, i2 in (511, 1023]
        {
            float xi = sx[i2], yi = sy[i2], zi = sz[i2], qi = sq[i2];
            for (int j = i2 + 1 + tid; j < AA; j += 256) {
                float dx = xi - sx[j], dy = yi - sy[j], dz = zi - sz[j];
                float r2 = dx*dx + dy*dy + dz*dz;
                e += qi * sq[j] * pair_coul(r2);
            }
        }
    }
    s_red[tid] = e; __syncthreads();
    for (int off = 128; off > 0; off >>= 1) {
        if (tid < off) s_red[tid] += s_red[tid + off];
        __syncthreads();
    }
    if (tid == 0) g_partial[b*8 + t] = s_red[0];
}

// ---------------- K5: finalize ----------------
__global__ void k5_final(float* __restrict__ out) {
    int b = threadIdx.x;
    if (b < BB) {
        float s = 0.f;
        #pragma unroll
        for (int t = 0; t < 8; t++) s += g_partial[b*8 + t];
        out[b] = 332.0636f * s;
    }
}

extern "C" void kernel_launch(void* const* d_in, const int* in_sizes, int n_in,
                              void* d_out, int out_size) {
    const float* e_z     = (const float*)d_in[0];
    const float* charge  = (const float*)d_in[1];
    const float* xyz     = (const float*)d_in[2];
    const float* W_lin   = (const float*)d_in[3];
    const float* b_lin   = (const float*)d_in[4];
    const float* k_plus  = (const float*)d_in[5];
    const float* k_minus = (const float*)d_in[6];
    const float* v_plus  = (const float*)d_in[7];
    const float* v_minus = (const float*)d_in[8];
    const float* Wr1     = (const float*)d_in[9];
    const float* Wr2     = (const float*)d_in[10];
    const float* Wout    = (const float*)d_in[11];
    const float* w_e     = (const float*)d_in[12];
    const float* q_tab   = (const float*)d_in[13];
    const int*   z       = (const int*)d_in[14];
    float* out = (float*)d_out;

    const int smem_k2 = (FF*FF*2 + MT*132 + MT + FF + FF) * (int)sizeof(float); // 200192
    cudaFuncSetAttribute(k2_mlp, cudaFuncAttributeMaxDynamicSharedMemorySize, smem_k2);

    k0_prep<<<1, 128>>>(W_lin, b_lin, k_plus, k_minus, Wout, w_e);
    k1_fused<<<NN/256, 256>>>(e_z, charge, w_e);
    k2_mlp<<<NN/MT, 512, smem_k2>>>(Wr1, Wr2, v_plus, v_minus, charge, z, q_tab);
    k3_correct<<<BB, 256>>>(charge);
    dim3 g4(8, BB);
    k4_pair<<<g4, 256>>>(xyz);
    k5_final<<<1, 32>>>(out);
}

// round 4
// speedup vs baseline: 1.9995x; 1.3816x over previous
#include <cuda_runtime.h>
#include <cuda_bf16.h>
#include <math.h>
#include <cstdint>

#define BB 32
#define AA 1024
#define FF 128
#define NN (BB*AA)

// ================= scratch =================
__device__ float g_u2[2][FF];
__device__ float g_bk2[2];
__device__ float g_wow[FF];
__device__ float g_num[NN];
__device__ float g_numpart[NN/256];
__device__ float g_ezwe[NN];
__device__ float g_pred[NN];
__device__ float g_partial[BB*8];
// W1^T / W2^T as bf16, layout Wt[n][k], row stride 136 (272 B): 128*136*2 = 34816 B each
__device__ uint4 g_W1bf4[2176];
__device__ uint4 g_W2bf4[2176];

__device__ __forceinline__ float fsilu(float x) {
    return __fdividef(x, 1.0f + __expf(-x));
}
__device__ __forceinline__ uint32_t packbf(float lo, float hi) {
    uint32_t r;
    asm("cvt.rn.satfinite.bf16x2.f32 %0, %1, %2;" : "=r"(r) : "f"(hi), "f"(lo));
    return r;
}
__device__ __forceinline__ uint32_t smem_u32(const void* p) {
    uint32_t a;
    asm("{ .reg .u64 t; cvta.to.shared.u64 t, %1; cvt.u32.u64 %0, t; }" : "=r"(a) : "l"(p));
    return a;
}
__device__ __forceinline__ void ldsm_x2(uint32_t& r0, uint32_t& r1, uint32_t addr) {
    asm volatile("ldmatrix.sync.aligned.m8n8.x2.shared.b16 {%0,%1}, [%2];"
                 : "=r"(r0), "=r"(r1) : "r"(addr));
}
__device__ __forceinline__ void mma16816(float* d, const uint32_t* a, uint32_t b0, uint32_t b1) {
    asm volatile("mma.sync.aligned.m16n8k16.row.col.f32.bf16.bf16.f32 "
                 "{%0,%1,%2,%3}, {%4,%5,%6,%7}, {%8,%9}, {%0,%1,%2,%3};"
                 : "+f"(d[0]), "+f"(d[1]), "+f"(d[2]), "+f"(d[3])
                 : "r"(a[0]), "r"(a[1]), "r"(a[2]), "r"(a[3]), "r"(b0), "r"(b1));
}

// ---------------- K0: tiny precompute ----------------
__global__ void k0_prep(const float* __restrict__ W_lin, const float* __restrict__ b_lin,
                        const float* __restrict__ kp, const float* __restrict__ km,
                        const float* __restrict__ Wout, const float* __restrict__ w_e) {
    int g = threadIdx.x;
    float up = 0.f, um = 0.f, wo = 0.f;
    #pragma unroll 4
    for (int f = 0; f < FF; f++) {
        float w = W_lin[g*FF + f];
        up += w * kp[f];
        um += w * km[f];
        wo += Wout[g*FF + f] * w_e[f];
    }
    g_u2[0][g] = up; g_u2[1][g] = um; g_wow[g] = wo;
    if (g == 0) {
        float bp = 0.f, bm = 0.f;
        for (int f = 0; f < FF; f++) { bp += b_lin[f]*kp[f]; bm += b_lin[f]*km[f]; }
        g_bk2[0] = bp; g_bk2[1] = bm;
    }
}

// ---------------- K0b: W1/W2 -> transposed bf16 (Wt[n][k], stride 136) --------
__global__ void k0b_wconv(const float* __restrict__ W1, const float* __restrict__ W2) {
    int i = blockIdx.x * 256 + threadIdx.x;      // 0..16383
    int k = i >> 7, n = i & 127;
    int off = n*136 + k;
    ((__nv_bfloat16*)g_W1bf4)[off] = __float2bfloat16(W1[k*FF + n]);
    ((__nv_bfloat16*)g_W2bf4)[off] = __float2bfloat16(W2[k*FF + n]);
}

// ---------------- K1: fused row dots, one pass over e_z ----------------
__global__ void k1_fused(const float* __restrict__ e_z, const float* __restrict__ charge,
                         const float* __restrict__ w_e) {
    __shared__ float s_u[FF];
    __shared__ float s_we[FF];
    __shared__ float s_red[256];
    int bb = blockIdx.x;
    int b  = bb >> 2;
    int tid = threadIdx.x;
    float c = charge[b];
    int sgn = (c >= 0.0f) ? 0 : 1;
    if (tid < FF) { s_u[tid] = g_u2[sgn][tid]; s_we[tid] = w_e[tid]; }
    __syncthreads();

    size_t n = (size_t)bb * 256 + tid;
    const float4* ez = (const float4*)(e_z + n*FF);
    float d1 = 0.f, d2 = 0.f;
    #pragma unroll
    for (int f4 = 0; f4 < 32; f4++) {
        float4 v = ez[f4];
        int f = f4*4;
        d1 += v.x*s_u[f]  + v.y*s_u[f+1]  + v.z*s_u[f+2]  + v.w*s_u[f+3];
        d2 += v.x*s_we[f] + v.y*s_we[f+1] + v.z*s_we[f+2] + v.w*s_we[f+3];
    }
    const float inv_sqrtF = 0.08838834764831845f;
    float arg = (d1 + g_bk2[sgn]) * inv_sqrtF;
    float num = fmaxf(arg, 0.f) + log1pf(expf(-fabsf(arg)));
    g_num[n] = num;
    g_ezwe[n] = d2;

    s_red[tid] = num;
    __syncthreads();
    for (int off = 128; off > 0; off >>= 1) {
        if (tid < off) s_red[tid] += s_red[tid + off];
        __syncthreads();
    }
    if (tid == 0) g_numpart[bb] = s_red[0];
}

// ---------------- K2: HMMA (mma.sync bf16) res-MLP, register-chained ----------
// smem: sW1 [0,34816) sW2 [34816,69632) s_a 69632 s_v 70144 s_wow 70656; total 71168
#define K2_SMEM 71168
__global__ void __launch_bounds__(256, 2)
k2_mma(const float* __restrict__ charge, const int* __restrict__ z,
       const float* __restrict__ q_tab,
       const float* __restrict__ vp, const float* __restrict__ vm) {
    extern __shared__ char smem[];
    float* s_a   = (float*)(smem + 69632);
    float* s_v   = (float*)(smem + 70144);
    float* s_wow = (float*)(smem + 70656);
    uint32_t sb = smem_u32(smem);

    int tid = threadIdx.x, wid = tid >> 5, lane = tid & 31;
    int m0 = blockIdx.x * 128;
    int b = m0 >> 10;
    float c = charge[b];
    const float* v = (c >= 0.f) ? vp : vm;

    uint4* dst1 = (uint4*)smem;
    uint4* dst2 = (uint4*)(smem + 34816);
    for (int i = tid; i < 2176; i += 256) { dst1[i] = g_W1bf4[i]; dst2[i] = g_W2bf4[i]; }
    if (tid < 128) {
        float tot = g_numpart[b*4] + g_numpart[b*4+1] + g_numpart[b*4+2] + g_numpart[b*4+3];
        s_a[tid]   = c * g_num[m0 + tid] / tot;
        s_v[tid]   = v[tid];
        s_wow[tid] = g_wow[tid];
    }
    __syncthreads();

    int quad = lane >> 2, qt = lane & 3;
    int mrow = wid * 16 + quad;              // block-local row for c0/c1 (+8 for c2/c3)
    float am0 = s_a[mrow], am8 = s_a[mrow + 8];

    // ldmatrix lane offset within an n-tile: lanes 0-7 -> rows n0..n0+7 @k0,
    // lanes 8-15 -> same rows @k0+8 (16B further).
    int ll = lane & 15;
    uint32_t boff = (uint32_t)((ll & 7) * 272 + (ll >> 3) * 16);

    // ---- GEMM1 A fragments: X = silu(a*v), computed analytically ----
    uint32_t af[8][4];
    #pragma unroll
    for (int s = 0; s < 8; s++) {
        int k0 = s*16 + qt*2;
        float v0 = s_v[k0], v1 = s_v[k0+1], v8 = s_v[k0+8], v9 = s_v[k0+9];
        af[s][0] = packbf(fsilu(am0*v0), fsilu(am0*v1));
        af[s][1] = packbf(fsilu(am8*v0), fsilu(am8*v1));
        af[s][2] = packbf(fsilu(am0*v8), fsilu(am0*v9));
        af[s][3] = packbf(fsilu(am8*v8), fsilu(am8*v9));
    }

    float acc[16][4];
    // ---- GEMM1: h1 = X @ W1  (B = Wt1 rows n, k-contig) ----
    #pragma unroll
    for (int nt = 0; nt < 16; nt++)
        #pragma unroll
        for (int i = 0; i < 4; i++) acc[nt][i] = 0.f;
    #pragma unroll
    for (int s = 0; s < 8; s++) {
        #pragma unroll
        for (int nt = 0; nt < 16; nt++) {
            uint32_t b0, b1;
            ldsm_x2(b0, b1, sb + (uint32_t)(nt*2176 + s*32) + boff);
            mma16816(acc[nt], af[s], b0, b1);
        }
    }

    // ---- chain: A2 fragments = silu(h1), accumulators -> fragments in-register
    #pragma unroll
    for (int s = 0; s < 8; s++) {
        af[s][0] = packbf(fsilu(acc[2*s][0]),   fsilu(acc[2*s][1]));
        af[s][1] = packbf(fsilu(acc[2*s][2]),   fsilu(acc[2*s][3]));
        af[s][2] = packbf(fsilu(acc[2*s+1][0]), fsilu(acc[2*s+1][1]));
        af[s][3] = packbf(fsilu(acc[2*s+1][2]), fsilu(acc[2*s+1][3]));
    }

    // ---- GEMM2: h2 = silu(h1) @ W2 ----
    #pragma unroll
    for (int nt = 0; nt < 16; nt++)
        #pragma unroll
        for (int i = 0; i < 4; i++) acc[nt][i] = 0.f;
    #pragma unroll
    for (int s = 0; s < 8; s++) {
        #pragma unroll
        for (int nt = 0; nt < 16; nt++) {
            uint32_t b0, b1;
            ldsm_x2(b0, b1, sb + (uint32_t)(34816 + nt*2176 + s*32) + boff);
            mma16816(acc[nt], af[s], b0, b1);
        }
    }

    // ---- epilogue: p_m = sum_n silu(a*v[n] + h2[n]) * wow[n] ----
    float p0 = 0.f, p8 = 0.f;
    #pragma unroll
    for (int nt = 0; nt < 16; nt++) {
        int n = nt*8 + qt*2;
        float vv0 = s_v[n], vv1 = s_v[n+1], w0 = s_wow[n], w1 = s_wow[n+1];
        p0 += fsilu(am0*vv0 + acc[nt][0]) * w0 + fsilu(am0*vv1 + acc[nt][1]) * w1;
        p8 += fsilu(am8*vv0 + acc[nt][2]) * w0 + fsilu(am8*vv1 + acc[nt][3]) * w1;
    }
    p0 += __shfl_xor_sync(0xffffffffu, p0, 1);
    p0 += __shfl_xor_sync(0xffffffffu, p0, 2);
    p8 += __shfl_xor_sync(0xffffffffu, p8, 1);
    p8 += __shfl_xor_sync(0xffffffffu, p8, 2);
    if (qt == 0) {
        int n = m0 + mrow;
        g_pred[n]     = g_ezwe[n]     + p0 + q_tab[z[n]];
        g_pred[n + 8] = g_ezwe[n + 8] + p8 + q_tab[z[n + 8]];
    }
}

// ---------------- K4: charge correction + O(A^2) switched Coulomb ----------------
__device__ __forceinline__ float pair_coul(float r2) {
    const float RON = 1.25f, INVW = 0.4f;
    const float RON2 = 1.5625f, ROFF2 = 14.0625f;
    if (r2 >= ROFF2) return rsqrtf(r2);
    if (r2 <= RON2)  return rsqrtf(r2 + 1.f);
    float r = sqrtf(r2);
    float arg = (r - RON) * INVW;
    float num = expf(-1.f / (1.f - arg));
    float den = expf(-1.f / arg);
    float fs = num / (num + den);
    return fs * rsqrtf(r2 + 1.f) + (1.f - fs) / r;
}

__global__ void k4_pair(const float* __restrict__ xyz, const float* __restrict__ charge) {
    int b = blockIdx.y; int t = blockIdx.x; int tid = threadIdx.x;
    __shared__ float sx[AA], sy[AA], sz[AA], sq[AA];
    __shared__ float s_red[256];
    float psum = 0.f;
    for (int a = tid; a < AA; a += 256) {
        size_t base = ((size_t)b*AA + a) * 3;
        sx[a] = xyz[base]; sy[a] = xyz[base+1]; sz[a] = xyz[base+2];
        float p = g_pred[b*AA + a];
        sq[a] = p; psum += p;
    }
    s_red[tid] = psum; __syncthreads();
    for (int off = 128; off > 0; off >>= 1) {
        if (tid < off) s_red[tid] += s_red[tid + off];
        __syncthreads();
    }
    float corr = (charge[b] - s_red[0]) * (1.0f / AA);
    __syncthreads();
    for (int a = tid; a < AA; a += 256) sq[a] += corr;
    __syncthreads();

    float e = 0.f;
    #pragma unroll 1
    for (int rr = 0; rr < 64; rr++) {
        int i = t*64 + rr;
        {
            float xi = sx[i], yi = sy[i], zi = sz[i], qi = sq[i];
            for (int j = i + 1 + tid; j < AA; j += 256) {
                float dx = xi - sx[j], dy = yi - sy[j], dz = zi - sz[j];
                float r2 = dx*dx + dy*dy + dz*dz;
                e += qi * sq[j] * pair_coul(r2);
            }
        }
        int i2 = AA - 1 - i;
        {
            float xi = sx[i2], yi = sy[i2], zi = sz[i2], qi = sq[i2];
            for (int j = i2 + 1 + tid; j < AA; j += 256) {
                float dx = xi - sx[j], dy = yi - sy[j], dz = zi - sz[j];
                float r2 = dx*dx + dy*dy + dz*dz;
                e += qi * sq[j] * pair_coul(r2);
            }
        }
    }
    s_red[tid] = e; __syncthreads();
    for (int off = 128; off > 0; off >>= 1) {
        if (tid < off) s_red[tid] += s_red[tid + off];
        __syncthreads();
    }
    if (tid == 0) g_partial[b*8 + t] = s_red[0];
}

// ---------------- K5: finalize ----------------
__global__ void k5_final(float* __restrict__ out) {
    int b = threadIdx.x;
    if (b < BB) {
        float s = 0.f;
        #pragma unroll
        for (int t = 0; t < 8; t++) s += g_partial[b*8 + t];
        out[b] = 332.0636f * s;
    }
}

extern "C" void kernel_launch(void* const* d_in, const int* in_sizes, int n_in,
                              void* d_out, int out_size) {
    const float* e_z     = (const float*)d_in[0];
    const float* charge  = (const float*)d_in[1];
    const float* xyz     = (const float*)d_in[2];
    const float* W_lin   = (const float*)d_in[3];
    const float* b_lin   = (const float*)d_in[4];
    const float* k_plus  = (const float*)d_in[5];
    const float* k_minus = (const float*)d_in[6];
    const float* v_plus  = (const float*)d_in[7];
    const float* v_minus = (const float*)d_in[8];
    const float* Wr1     = (const float*)d_in[9];
    const float* Wr2     = (const float*)d_in[10];
    const float* Wout    = (const float*)d_in[11];
    const float* w_e     = (const float*)d_in[12];
    const float* q_tab   = (const float*)d_in[13];
    const int*   z       = (const int*)d_in[14];
    float* out = (float*)d_out;

    cudaFuncSetAttribute(k2_mma, cudaFuncAttributeMaxDynamicSharedMemorySize, K2_SMEM);

    k0_prep<<<1, 128>>>(W_lin, b_lin, k_plus, k_minus, Wout, w_e);
    k0b_wconv<<<64, 256>>>(Wr1, Wr2);
    k1_fused<<<NN/256, 256>>>(e_z, charge, w_e);
    k2_mma<<<NN/128, 256, K2_SMEM>>>(charge, z, q_tab, v_plus, v_minus);
    dim3 g4(8, BB);
    k4_pair<<<g4, 256>>>(xyz, charge);
    k5_final<<<1, 32>>>(out);
}

// round 5
// speedup vs baseline: 2.9805x; 1.4906x over previous
#include <cuda_runtime.h>
#include <cuda_bf16.h>
#include <math.h>
#include <cstdint>

#define BB 32
#define AA 1024
#define FF 128
#define NN (BB*AA)

// ================= scratch =================
__device__ float g_u2[2][FF];
__device__ float g_bk2[2];
__device__ float g_wow[FF];
__device__ float g_num[NN];
__device__ float g_numpart[NN/256];
__device__ float g_ezwe[NN];
__device__ float g_pred[NN];
__device__ float g_partial[BB*8];
__device__ int   g_cnt[BB];
// W1^T / W2^T as bf16, layout Wt[n][k], row stride 136 (272 B): 128*136*2 = 34816 B each
__device__ uint4 g_W1bf4[2176];
__device__ uint4 g_W2bf4[2176];

__device__ __forceinline__ float fsilu(float x) {
    return __fdividef(x, 1.0f + __expf(-x));
}
__device__ __forceinline__ uint32_t packbf(float lo, float hi) {
    uint32_t r;
    asm("cvt.rn.satfinite.bf16x2.f32 %0, %1, %2;" : "=r"(r) : "f"(hi), "f"(lo));
    return r;
}
__device__ __forceinline__ uint32_t smem_u32(const void* p) {
    uint32_t a;
    asm("{ .reg .u64 t; cvta.to.shared.u64 t, %1; cvt.u32.u64 %0, t; }" : "=r"(a) : "l"(p));
    return a;
}
__device__ __forceinline__ void ldsm_x4(uint32_t& r0, uint32_t& r1, uint32_t& r2, uint32_t& r3,
                                        uint32_t addr) {
    asm volatile("ldmatrix.sync.aligned.m8n8.x4.shared.b16 {%0,%1,%2,%3}, [%4];"
                 : "=r"(r0), "=r"(r1), "=r"(r2), "=r"(r3) : "r"(addr));
}
__device__ __forceinline__ void mma16816(float* d, const uint32_t* a, uint32_t b0, uint32_t b1) {
    asm volatile("mma.sync.aligned.m16n8k16.row.col.f32.bf16.bf16.f32 "
                 "{%0,%1,%2,%3}, {%4,%5,%6,%7}, {%8,%9}, {%0,%1,%2,%3};"
                 : "+f"(d[0]), "+f"(d[1]), "+f"(d[2]), "+f"(d[3])
                 : "r"(a[0]), "r"(a[1]), "r"(a[2]), "r"(a[3]), "r"(b0), "r"(b1));
}

// ---------------- K0f: fused precompute (weight convert + projected vectors) ----
// grid 193 x 256:
//   blocks 0..63   : W1/W2 -> transposed bf16 Wt[n][k], stride 136
//   blocks 64..191 : g = blk-64: g_u2[0/1][g] = W_lin[g,:].k{p,m}; g_wow[g] = Wout[g,:].w_e
//   block 192      : g_bk2
__global__ void k0f(const float* __restrict__ W1, const float* __restrict__ W2,
                    const float* __restrict__ W_lin, const float* __restrict__ b_lin,
                    const float* __restrict__ kp, const float* __restrict__ km,
                    const float* __restrict__ Wout, const float* __restrict__ w_e) {
    int blk = blockIdx.x, tid = threadIdx.x;
    if (blk < 64) {
        int i = blk * 256 + tid;                 // 0..16383
        int k = i >> 7, n = i & 127;
        int off = n*136 + k;
        ((__nv_bfloat16*)g_W1bf4)[off] = __float2bfloat16(W1[k*FF + n]);
        ((__nv_bfloat16*)g_W2bf4)[off] = __float2bfloat16(W2[k*FF + n]);
        return;
    }
    __shared__ float r0[256], r1[256], r2[256];
    if (blk < 192) {
        int g = blk - 64;
        float a0 = 0.f, a1 = 0.f, a2 = 0.f;
        if (tid < 128) {
            float w = W_lin[g*FF + tid];
            a0 = w * kp[tid];
            a1 = w * km[tid];
            a2 = Wout[g*FF + tid] * w_e[tid];
        }
        r0[tid] = a0; r1[tid] = a1; r2[tid] = a2;
        __syncthreads();
        for (int off = 128; off > 0; off >>= 1) {
            if (tid < off) { r0[tid] += r0[tid+off]; r1[tid] += r1[tid+off]; r2[tid] += r2[tid+off]; }
            __syncthreads();
        }
        if (tid == 0) { g_u2[0][g] = r0[0]; g_u2[1][g] = r1[0]; g_wow[g] = r2[0]; }
        return;
    }
    // block 192: bk2
    float a0 = 0.f, a1 = 0.f;
    if (tid < 128) { float bl = b_lin[tid]; a0 = bl * kp[tid]; a1 = bl * km[tid]; }
    r0[tid] = a0; r1[tid] = a1;
    __syncthreads();
    for (int off = 128; off > 0; off >>= 1) {
        if (tid < off) { r0[tid] += r0[tid+off]; r1[tid] += r1[tid+off]; }
        __syncthreads();
    }
    if (tid == 0) { g_bk2[0] = r0[0]; g_bk2[1] = r1[0]; }
}

// ---------------- K1: fused row dots, one pass over e_z ----------------
__global__ void k1_fused(const float* __restrict__ e_z, const float* __restrict__ charge,
                         const float* __restrict__ w_e) {
    __shared__ float s_u[FF];
    __shared__ float s_we[FF];
    __shared__ float s_red[256];
    int bb = blockIdx.x;
    int b  = bb >> 2;
    int tid = threadIdx.x;
    if (bb == 0 && tid < BB) g_cnt[tid] = 0;     // reset k4 completion counters
    float c = charge[b];
    int sgn = (c >= 0.0f) ? 0 : 1;
    if (tid < FF) { s_u[tid] = g_u2[sgn][tid]; s_we[tid] = w_e[tid]; }
    __syncthreads();

    size_t n = (size_t)bb * 256 + tid;
    const float4* ez = (const float4*)(e_z + n*FF);
    float d1 = 0.f, d2 = 0.f;
    #pragma unroll
    for (int f4 = 0; f4 < 32; f4++) {
        float4 v = ez[f4];
        int f = f4*4;
        d1 += v.x*s_u[f]  + v.y*s_u[f+1]  + v.z*s_u[f+2]  + v.w*s_u[f+3];
        d2 += v.x*s_we[f] + v.y*s_we[f+1] + v.z*s_we[f+2] + v.w*s_we[f+3];
    }
    const float inv_sqrtF = 0.08838834764831845f;
    float arg = (d1 + g_bk2[sgn]) * inv_sqrtF;
    float num = fmaxf(arg, 0.f) + log1pf(expf(-fabsf(arg)));
    g_num[n] = num;
    g_ezwe[n] = d2;

    s_red[tid] = num;
    __syncthreads();
    for (int off = 128; off > 0; off >>= 1) {
        if (tid < off) s_red[tid] += s_red[tid + off];
        __syncthreads();
    }
    if (tid == 0) g_numpart[bb] = s_red[0];
}

// ---------------- K2: HMMA (mma.sync bf16) res-MLP, register-chained ----------
// smem: sW1 [0,34816) sW2 [34816,69632) s_a 69632 s_v 70144 s_wow 70656; total 71168
#define K2_SMEM 71168
__global__ void __launch_bounds__(256, 2)
k2_mma(const float* __restrict__ charge, const int* __restrict__ z,
       const float* __restrict__ q_tab,
       const float* __restrict__ vp, const float* __restrict__ vm) {
    extern __shared__ char smem[];
    float* s_a   = (float*)(smem + 69632);
    float* s_v   = (float*)(smem + 70144);
    float* s_wow = (float*)(smem + 70656);
    uint32_t sb = smem_u32(smem);

    int tid = threadIdx.x, wid = tid >> 5, lane = tid & 31;
    int m0 = blockIdx.x * 128;
    int b = m0 >> 10;
    float c = charge[b];
    const float* v = (c >= 0.f) ? vp : vm;

    uint4* dst1 = (uint4*)smem;
    uint4* dst2 = (uint4*)(smem + 34816);
    for (int i = tid; i < 2176; i += 256) { dst1[i] = g_W1bf4[i]; dst2[i] = g_W2bf4[i]; }
    if (tid < 128) {
        float tot = g_numpart[b*4] + g_numpart[b*4+1] + g_numpart[b*4+2] + g_numpart[b*4+3];
        s_a[tid]   = c * g_num[m0 + tid] / tot;
        s_v[tid]   = v[tid];
        s_wow[tid] = g_wow[tid];
    }
    __syncthreads();

    int quad = lane >> 2, qt = lane & 3;
    int mrow = wid * 16 + quad;              // block-local row for c0/c1 (+8 for c2/c3)
    float am0 = s_a[mrow], am8 = s_a[mrow + 8];

    // x4 ldmatrix lane address: matrices {nt rows k0, nt rows k0+8, nt+1 rows k0, nt+1 rows k0+8}
    int rl = ((lane >> 4) << 3) | (lane & 7);           // row-within-16
    uint32_t boff = (uint32_t)(rl * 272 + ((lane >> 3) & 1) * 16);

    // ---- GEMM1 A fragments: X = silu(a*v), computed analytically ----
    uint32_t af[8][4];
    #pragma unroll
    for (int s = 0; s < 8; s++) {
        int k0 = s*16 + qt*2;
        float v0 = s_v[k0], v1 = s_v[k0+1], v8 = s_v[k0+8], v9 = s_v[k0+9];
        af[s][0] = packbf(fsilu(am0*v0), fsilu(am0*v1));
        af[s][1] = packbf(fsilu(am8*v0), fsilu(am8*v1));
        af[s][2] = packbf(fsilu(am0*v8), fsilu(am0*v9));
        af[s][3] = packbf(fsilu(am8*v8), fsilu(am8*v9));
    }

    float acc[16][4];
    // ---- GEMM1: h1 = X @ W1 ----
    #pragma unroll
    for (int nt = 0; nt < 16; nt++)
        #pragma unroll
        for (int i = 0; i < 4; i++) acc[nt][i] = 0.f;
    #pragma unroll
    for (int s = 0; s < 8; s++) {
        #pragma unroll
        for (int np = 0; np < 8; np++) {
            uint32_t b0, b1, b2, b3;
            ldsm_x4(b0, b1, b2, b3, sb + (uint32_t)(np*4352 + s*32) + boff);
            mma16816(acc[2*np],   af[s], b0, b1);
            mma16816(acc[2*np+1], af[s], b2, b3);
        }
    }

    // ---- chain: A2 fragments = silu(h1) in-register ----
    #pragma unroll
    for (int s = 0; s < 8; s++) {
        af[s][0] = packbf(fsilu(acc[2*s][0]),   fsilu(acc[2*s][1]));
        af[s][1] = packbf(fsilu(acc[2*s][2]),   fsilu(acc[2*s][3]));
        af[s][2] = packbf(fsilu(acc[2*s+1][0]), fsilu(acc[2*s+1][1]));
        af[s][3] = packbf(fsilu(acc[2*s+1][2]), fsilu(acc[2*s+1][3]));
    }

    // ---- GEMM2: h2 = silu(h1) @ W2 ----
    #pragma unroll
    for (int nt = 0; nt < 16; nt++)
        #pragma unroll
        for (int i = 0; i < 4; i++) acc[nt][i] = 0.f;
    #pragma unroll
    for (int s = 0; s < 8; s++) {
        #pragma unroll
        for (int np = 0; np < 8; np++) {
            uint32_t b0, b1, b2, b3;
            ldsm_x4(b0, b1, b2, b3, sb + (uint32_t)(34816 + np*4352 + s*32) + boff);
            mma16816(acc[2*np],   af[s], b0, b1);
            mma16816(acc[2*np+1], af[s], b2, b3);
        }
    }

    // ---- epilogue: p_m = sum_n silu(a*v[n] + h2[n]) * wow[n] ----
    float p0 = 0.f, p8 = 0.f;
    #pragma unroll
    for (int nt = 0; nt < 16; nt++) {
        int n = nt*8 + qt*2;
        float vv0 = s_v[n], vv1 = s_v[n+1], w0 = s_wow[n], w1 = s_wow[n+1];
        p0 += fsilu(am0*vv0 + acc[nt][0]) * w0 + fsilu(am0*vv1 + acc[nt][1]) * w1;
        p8 += fsilu(am8*vv0 + acc[nt][2]) * w0 + fsilu(am8*vv1 + acc[nt][3]) * w1;
    }
    p0 += __shfl_xor_sync(0xffffffffu, p0, 1);
    p0 += __shfl_xor_sync(0xffffffffu, p0, 2);
    p8 += __shfl_xor_sync(0xffffffffu, p8, 1);
    p8 += __shfl_xor_sync(0xffffffffu, p8, 2);
    if (qt == 0) {
        int n = m0 + mrow;
        g_pred[n]     = g_ezwe[n]     + p0 + q_tab[z[n]];
        g_pred[n + 8] = g_ezwe[n + 8] + p8 + q_tab[z[n + 8]];
    }
}

// ---------------- K4: charge correction + O(A^2) switched Coulomb + finalize ----
__device__ __forceinline__ float pair_coul(float r2) {
    const float RON = 1.25f, INVW = 0.4f;
    const float RON2 = 1.5625f, ROFF2 = 14.0625f;
    if (r2 >= ROFF2) return rsqrtf(r2);
    if (r2 <= RON2)  return rsqrtf(r2 + 1.f);
    float r = sqrtf(r2);
    float arg = (r - RON) * INVW;
    float num = expf(-1.f / (1.f - arg));
    float den = expf(-1.f / arg);
    float fs = num / (num + den);
    return fs * rsqrtf(r2 + 1.f) + (1.f - fs) / r;
}

__global__ void k4_pair(const float* __restrict__ xyz, const float* __restrict__ charge,
                        float* __restrict__ out) {
    int b = blockIdx.y; int t = blockIdx.x; int tid = threadIdx.x;
    __shared__ float4 sp[AA];
    __shared__ float s_red[256];
    float psum = 0.f;
    for (int a = tid; a < AA; a += 256) {
        size_t base = ((size_t)b*AA + a) * 3;
        float p = g_pred[b*AA + a];
        sp[a] = make_float4(xyz[base], xyz[base+1], xyz[base+2], p);
        psum += p;
    }
    s_red[tid] = psum; __syncthreads();
    for (int off = 128; off > 0; off >>= 1) {
        if (tid < off) s_red[tid] += s_red[tid + off];
        __syncthreads();
    }
    float corr = (charge[b] - s_red[0]) * (1.0f / AA);
    __syncthreads();
    for (int a = tid; a < AA; a += 256) sp[a].w += corr;
    __syncthreads();

    // 4 threads per bow-tie pair-row: long strided loops (j += 4)
    int pr = tid >> 2, tq = tid & 3;
    int i  = t*64 + pr;                 // in [0, 512)
    int i2 = AA - 1 - i;                // mirrored, in [512, 1024)
    float e = 0.f;
    {
        float4 pi = sp[i];
        #pragma unroll 2
        for (int j = i + 1 + tq; j < AA; j += 4) {
            float4 pj = sp[j];
            float dx = pi.x - pj.x, dy = pi.y - pj.y, dz = pi.z - pj.z;
            float r2 = dx*dx + dy*dy + dz*dz;
            e += pi.w * pj.w * pair_coul(r2);
        }
    }
    {
        float4 pi = sp[i2];
        #pragma unroll 2
        for (int j = i2 + 1 + tq; j < AA; j += 4) {
            float4 pj = sp[j];
            float dx = pi.x - pj.x, dy = pi.y - pj.y, dz = pi.z - pj.z;
            float r2 = dx*dx + dy*dy + dz*dz;
            e += pi.w * pj.w * pair_coul(r2);
        }
    }
    s_red[tid] = e; __syncthreads();
    for (int off = 128; off > 0; off >>= 1) {
        if (tid < off) s_red[tid] += s_red[tid + off];
        __syncthreads();
    }
    if (tid == 0) {
        g_partial[b*8 + t] = s_red[0];
        __threadfence();
        int done = atomicAdd(&g_cnt[b], 1);
        if (done == 7) {  // last block of this molecule: deterministic fixed-order sum
            volatile float* gp = g_partial;
            float s = 0.f;
            #pragma unroll
            for (int tt = 0; tt < 8; tt++) s += gp[b*8 + tt];
            out[b] = 332.0636f * s;
        }
    }
}

extern "C" void kernel_launch(void* const* d_in, const int* in_sizes, int n_in,
                              void* d_out, int out_size) {
    const float* e_z     = (const float*)d_in[0];
    const float* charge  = (const float*)d_in[1];
    const float* xyz     = (const float*)d_in[2];
    const float* W_lin   = (const float*)d_in[3];
    const float* b_lin   = (const float*)d_in[4];
    const float* k_plus  = (const float*)d_in[5];
    const float* k_minus = (const float*)d_in[6];
    const float* v_plus  = (const float*)d_in[7];
    const float* v_minus = (const float*)d_in[8];
    const float* Wr1     = (const float*)d_in[9];
    const float* Wr2     = (const float*)d_in[10];
    const float* Wout    = (const float*)d_in[11];
    const float* w_e     = (const float*)d_in[12];
    const float* q_tab   = (const float*)d_in[13];
    const int*   z       = (const int*)d_in[14];
    float* out = (float*)d_out;

    cudaFuncSetAttribute(k2_mma, cudaFuncAttributeMaxDynamicSharedMemorySize, K2_SMEM);

    k0f<<<193, 256>>>(Wr1, Wr2, W_lin, b_lin, k_plus, k_minus, Wout, w_e);
    k1_fused<<<NN/256, 256>>>(e_z, charge, w_e);
    k2_mma<<<NN/128, 256, K2_SMEM>>>(charge, z, q_tab, v_plus, v_minus);
    dim3 g4(8, BB);
    k4_pair<<<g4, 256>>>(xyz, charge, out);
}

// round 6
// speedup vs baseline: 5.4011x; 1.8122x over previous
#include <cuda_runtime.h>
#include <cuda_bf16.h>
#include <math.h>
#include <cstdint>

#define BB 32
#define AA 1024
#define FF 128
#define NN (BB*AA)

// ================= scratch =================
__device__ float g_u2[2][FF];
__device__ float g_bk2[2];
__device__ float g_wow[FF];
__device__ float g_num[NN];
__device__ float g_numpart[NN/256];
__device__ float g_ezwe[NN];
__device__ float g_pred[NN];
__device__ float g_partial[BB*16];
__device__ int   g_cnt[BB];
// W1^T / W2^T as bf16, layout Wt[n][k], row stride 136 (272 B): 128*136*2 = 34816 B each
__device__ uint4 g_W1bf4[2176];
__device__ uint4 g_W2bf4[2176];

__device__ __forceinline__ float fsilu(float x) {
    return __fdividef(x, 1.0f + __expf(-x));
}
__device__ __forceinline__ uint32_t packbf(float lo, float hi) {
    uint32_t r;
    asm("cvt.rn.satfinite.bf16x2.f32 %0, %1, %2;" : "=r"(r) : "f"(hi), "f"(lo));
    return r;
}
__device__ __forceinline__ uint32_t smem_u32(const void* p) {
    uint32_t a;
    asm("{ .reg .u64 t; cvta.to.shared.u64 t, %1; cvt.u32.u64 %0, t; }" : "=r"(a) : "l"(p));
    return a;
}
__device__ __forceinline__ void ldsm_x4(uint32_t& r0, uint32_t& r1, uint32_t& r2, uint32_t& r3,
                                        uint32_t addr) {
    asm volatile("ldmatrix.sync.aligned.m8n8.x4.shared.b16 {%0,%1,%2,%3}, [%4];"
                 : "=r"(r0), "=r"(r1), "=r"(r2), "=r"(r3) : "r"(addr));
}
__device__ __forceinline__ void mma16816(float* d, const uint32_t* a, uint32_t b0, uint32_t b1) {
    asm volatile("mma.sync.aligned.m16n8k16.row.col.f32.bf16.bf16.f32 "
                 "{%0,%1,%2,%3}, {%4,%5,%6,%7}, {%8,%9}, {%0,%1,%2,%3};"
                 : "+f"(d[0]), "+f"(d[1]), "+f"(d[2]), "+f"(d[3])
                 : "r"(a[0]), "r"(a[1]), "r"(a[2]), "r"(a[3]), "r"(b0), "r"(b1));
}

// ---------------- K0f: fused precompute (weight convert + projected vectors) ----
__global__ void k0f(const float* __restrict__ W1, const float* __restrict__ W2,
                    const float* __restrict__ W_lin, const float* __restrict__ b_lin,
                    const float* __restrict__ kp, const float* __restrict__ km,
                    const float* __restrict__ Wout, const float* __restrict__ w_e) {
    int blk = blockIdx.x, tid = threadIdx.x;
    if (blk < 64) {
        int i = blk * 256 + tid;                 // 0..16383
        int k = i >> 7, n = i & 127;
        int off = n*136 + k;
        ((__nv_bfloat16*)g_W1bf4)[off] = __float2bfloat16(W1[k*FF + n]);
        ((__nv_bfloat16*)g_W2bf4)[off] = __float2bfloat16(W2[k*FF + n]);
        return;
    }
    __shared__ float r0[256], r1[256], r2[256];
    if (blk < 192) {
        int g = blk - 64;
        float a0 = 0.f, a1 = 0.f, a2 = 0.f;
        if (tid < 128) {
            float w = W_lin[g*FF + tid];
            a0 = w * kp[tid];
            a1 = w * km[tid];
            a2 = Wout[g*FF + tid] * w_e[tid];
        }
        r0[tid] = a0; r1[tid] = a1; r2[tid] = a2;
        __syncthreads();
        for (int off = 128; off > 0; off >>= 1) {
            if (tid < off) { r0[tid] += r0[tid+off]; r1[tid] += r1[tid+off]; r2[tid] += r2[tid+off]; }
            __syncthreads();
        }
        if (tid == 0) { g_u2[0][g] = r0[0]; g_u2[1][g] = r1[0]; g_wow[g] = r2[0]; }
        return;
    }
    float a0 = 0.f, a1 = 0.f;
    if (tid < 128) { float bl = b_lin[tid]; a0 = bl * kp[tid]; a1 = bl * km[tid]; }
    r0[tid] = a0; r1[tid] = a1;
    __syncthreads();
    for (int off = 128; off > 0; off >>= 1) {
        if (tid < off) { r0[tid] += r0[tid+off]; r1[tid] += r1[tid+off]; }
        __syncthreads();
    }
    if (tid == 0) { g_bk2[0] = r0[0]; g_bk2[1] = r1[0]; }
}

// ---------------- K1: fused row dots, one pass over e_z ----------------
__global__ void k1_fused(const float* __restrict__ e_z, const float* __restrict__ charge,
                         const float* __restrict__ w_e) {
    __shared__ float s_u[FF];
    __shared__ float s_we[FF];
    __shared__ float s_red[256];
    int bb = blockIdx.x;
    int b  = bb >> 2;
    int tid = threadIdx.x;
    if (bb == 0 && tid < BB) g_cnt[tid] = 0;     // reset k4 completion counters
    float c = charge[b];
    int sgn = (c >= 0.0f) ? 0 : 1;
    if (tid < FF) { s_u[tid] = g_u2[sgn][tid]; s_we[tid] = w_e[tid]; }
    __syncthreads();

    size_t n = (size_t)bb * 256 + tid;
    const float4* ez = (const float4*)(e_z + n*FF);
    float d1 = 0.f, d2 = 0.f;
    #pragma unroll
    for (int f4 = 0; f4 < 32; f4++) {
        float4 v = ez[f4];
        int f = f4*4;
        d1 += v.x*s_u[f]  + v.y*s_u[f+1]  + v.z*s_u[f+2]  + v.w*s_u[f+3];
        d2 += v.x*s_we[f] + v.y*s_we[f+1] + v.z*s_we[f+2] + v.w*s_we[f+3];
    }
    const float inv_sqrtF = 0.08838834764831845f;
    float arg = (d1 + g_bk2[sgn]) * inv_sqrtF;
    float num = fmaxf(arg, 0.f) + log1pf(expf(-fabsf(arg)));
    g_num[n] = num;
    g_ezwe[n] = d2;

    s_red[tid] = num;
    __syncthreads();
    for (int off = 128; off > 0; off >>= 1) {
        if (tid < off) s_red[tid] += s_red[tid + off];
        __syncthreads();
    }
    if (tid == 0) g_numpart[bb] = s_red[0];
}

// ---------------- K2: HMMA (mma.sync bf16) res-MLP, register-chained ----------
// smem: sW1 [0,34816) sW2 [34816,69632) s_a 69632 s_v 70144 s_wow 70656; total 71168
#define K2_SMEM 71168
__global__ void __launch_bounds__(256, 2)
k2_mma(const float* __restrict__ charge, const int* __restrict__ z,
       const float* __restrict__ q_tab,
       const float* __restrict__ vp, const float* __restrict__ vm) {
    extern __shared__ char smem[];
    float* s_a   = (float*)(smem + 69632);
    float* s_v   = (float*)(smem + 70144);
    float* s_wow = (float*)(smem + 70656);
    uint32_t sb = smem_u32(smem);

    int tid = threadIdx.x, wid = tid >> 5, lane = tid & 31;
    int m0 = blockIdx.x * 128;
    int b = m0 >> 10;
    float c = charge[b];
    const float* v = (c >= 0.f) ? vp : vm;

    uint4* dst1 = (uint4*)smem;
    uint4* dst2 = (uint4*)(smem + 34816);
    for (int i = tid; i < 2176; i += 256) { dst1[i] = g_W1bf4[i]; dst2[i] = g_W2bf4[i]; }
    if (tid < 128) {
        float tot = g_numpart[b*4] + g_numpart[b*4+1] + g_numpart[b*4+2] + g_numpart[b*4+3];
        s_a[tid]   = c * g_num[m0 + tid] / tot;
        s_v[tid]   = v[tid];
        s_wow[tid] = g_wow[tid];
    }
    __syncthreads();

    int quad = lane >> 2, qt = lane & 3;
    int mrow = wid * 16 + quad;
    float am0 = s_a[mrow], am8 = s_a[mrow + 8];

    int rl = ((lane >> 4) << 3) | (lane & 7);
    uint32_t boff = (uint32_t)(rl * 272 + ((lane >> 3) & 1) * 16);

    uint32_t af[8][4];
    #pragma unroll
    for (int s = 0; s < 8; s++) {
        int k0 = s*16 + qt*2;
        float v0 = s_v[k0], v1 = s_v[k0+1], v8 = s_v[k0+8], v9 = s_v[k0+9];
        af[s][0] = packbf(fsilu(am0*v0), fsilu(am0*v1));
        af[s][1] = packbf(fsilu(am8*v0), fsilu(am8*v1));
        af[s][2] = packbf(fsilu(am0*v8), fsilu(am0*v9));
        af[s][3] = packbf(fsilu(am8*v8), fsilu(am8*v9));
    }

    float acc[16][4];
    #pragma unroll
    for (int nt = 0; nt < 16; nt++)
        #pragma unroll
        for (int i = 0; i < 4; i++) acc[nt][i] = 0.f;
    #pragma unroll
    for (int s = 0; s < 8; s++) {
        #pragma unroll
        for (int np = 0; np < 8; np++) {
            uint32_t b0, b1, b2, b3;
            ldsm_x4(b0, b1, b2, b3, sb + (uint32_t)(np*4352 + s*32) + boff);
            mma16816(acc[2*np],   af[s], b0, b1);
            mma16816(acc[2*np+1], af[s], b2, b3);
        }
    }

    #pragma unroll
    for (int s = 0; s < 8; s++) {
        af[s][0] = packbf(fsilu(acc[2*s][0]),   fsilu(acc[2*s][1]));
        af[s][1] = packbf(fsilu(acc[2*s][2]),   fsilu(acc[2*s][3]));
        af[s][2] = packbf(fsilu(acc[2*s+1][0]), fsilu(acc[2*s+1][1]));
        af[s][3] = packbf(fsilu(acc[2*s+1][2]), fsilu(acc[2*s+1][3]));
    }

    #pragma unroll
    for (int nt = 0; nt < 16; nt++)
        #pragma unroll
        for (int i = 0; i < 4; i++) acc[nt][i] = 0.f;
    #pragma unroll
    for (int s = 0; s < 8; s++) {
        #pragma unroll
        for (int np = 0; np < 8; np++) {
            uint32_t b0, b1, b2, b3;
            ldsm_x4(b0, b1, b2, b3, sb + (uint32_t)(34816 + np*4352 + s*32) + boff);
            mma16816(acc[2*np],   af[s], b0, b1);
            mma16816(acc[2*np+1], af[s], b2, b3);
        }
    }

    float p0 = 0.f, p8 = 0.f;
    #pragma unroll
    for (int nt = 0; nt < 16; nt++) {
        int n = nt*8 + qt*2;
        float vv0 = s_v[n], vv1 = s_v[n+1], w0 = s_wow[n], w1 = s_wow[n+1];
        p0 += fsilu(am0*vv0 + acc[nt][0]) * w0 + fsilu(am0*vv1 + acc[nt][1]) * w1;
        p8 += fsilu(am8*vv0 + acc[nt][2]) * w0 + fsilu(am8*vv1 + acc[nt][3]) * w1;
    }
    p0 += __shfl_xor_sync(0xffffffffu, p0, 1);
    p0 += __shfl_xor_sync(0xffffffffu, p0, 2);
    p8 += __shfl_xor_sync(0xffffffffu, p8, 1);
    p8 += __shfl_xor_sync(0xffffffffu, p8, 2);
    if (qt == 0) {
        int n = m0 + mrow;
        g_pred[n]     = g_ezwe[n]     + p0 + q_tab[z[n]];
        g_pred[n + 8] = g_ezwe[n + 8] + p8 + q_tab[z[n + 8]];
    }
}

// ---------------- K4: correction + O(A^2) Coulomb, i-tiled & branch-free ----
#define ROFF2C 14.0625f
#define K_STASH 28

__device__ __forceinline__ float flush_stash(const float4* sp, uint32_t* stash, int& scnt) {
    float e = 0.f;
    for (int s = 0; s < scnt; s++) {
        uint32_t vv = stash[s];
        int j = vv >> 10, i = vv & 1023;
        float4 pi = sp[i], pj = sp[j];
        float dx = pi.x-pj.x, dy = pi.y-pj.y, dz = pi.z-pj.z;
        float r2 = dx*dx + dy*dy + dz*dz;
        float rinv = rsqrtf(r2);
        float r = r2 * rinv;
        float arg = (r - 1.25f) * 0.4f;
        arg = fminf(fmaxf(arg, 1e-7f), 1.f - 1e-7f);
        float num = __expf(__fdividef(-1.f, 1.f - arg));
        float den = __expf(__fdividef(-1.f, arg));
        float fs  = __fdividef(num, num + den);
        e += pi.w * pj.w * fs * (rsqrtf(r2 + 1.f) - rinv);
    }
    scnt = 0;
    return e;
}

__global__ void __launch_bounds__(128, 4)
k4_pair(const float* __restrict__ xyz, const float* __restrict__ charge,
        float* __restrict__ out) {
    int b = blockIdx.y, t = blockIdx.x, tid = threadIdx.x;
    __shared__ float4 sp[AA];
    __shared__ float s_red[128];
    float psum = 0.f;
    for (int a = tid; a < AA; a += 128) {
        size_t base = ((size_t)b*AA + a) * 3;
        float p = g_pred[b*AA + a];
        sp[a] = make_float4(xyz[base], xyz[base+1], xyz[base+2], p);
        psum += p;
    }
    s_red[tid] = psum; __syncthreads();
    for (int off = 64; off > 0; off >>= 1) {
        if (tid < off) s_red[tid] += s_red[tid + off];
        __syncthreads();
    }
    float corr = (charge[b] - s_red[0]) * (1.0f / AA);
    __syncthreads();
    for (int a = tid; a < AA; a += 128) sp[a].w += corr;
    __syncthreads();

    int wid = tid >> 5, lane = tid & 31;
    int wglob = t*4 + wid;                 // 0..63
    uint32_t stash[K_STASH];
    int scnt = 0;
    float e0 = 0.f, e1 = 0.f;

    #pragma unroll 1
    for (int tt = 0; tt < 2; tt++) {
        int base = (tt == 0) ? (wglob * 8) : (1016 - wglob * 8);
        float xi[8], yi[8], zi[8], qi[8];
        #pragma unroll
        for (int r = 0; r < 8; r++) {
            float4 p = sp[base + r];
            xi[r] = p.x; yi[r] = p.y; zi[r] = p.z; qi[r] = p.w;
        }
        // intra-tile corner (28 pairs), one predicated step
        {
            bool lv = (lane >= 1) && (lane < 8);
            int jc = base + (lv ? lane : 0);
            float4 pj = sp[jc];
            #pragma unroll
            for (int r = 0; r < 8; r++) {
                bool val = lv && (lane > r);
                float dx = xi[r]-pj.x, dy = yi[r]-pj.y, dz = zi[r]-pj.z;
                float r2 = dx*dx + dy*dy + dz*dz;
                float r2s = val ? r2 : 1.0f;
                float qq  = val ? qi[r]*pj.w : 0.0f;
                e0 += qq * rsqrtf(r2s);
                if (val && r2 < ROFF2C)
                    stash[scnt++] = ((uint32_t)jc << 10) | (uint32_t)(base + r);
            }
        }
        // main sweep: lanes stream distinct j, shared i-tile in registers
        for (int j = base + 8 + lane; j < AA; j += 32) {
            float4 pj = sp[j];
            #pragma unroll
            for (int r = 0; r < 8; r++) {
                float dx = xi[r]-pj.x, dy = yi[r]-pj.y, dz = zi[r]-pj.z;
                float r2 = dx*dx + dy*dy + dz*dz;
                float qq = qi[r]*pj.w;
                float rv = rsqrtf(r2);
                if (r & 1) e1 += qq*rv; else e0 += qq*rv;
                if (r2 < ROFF2C)
                    stash[scnt++] = ((uint32_t)j << 10) | (uint32_t)(base + r);
            }
            if (scnt >= K_STASH - 8) e0 += flush_stash(sp, stash, scnt);
        }
    }
    e0 += flush_stash(sp, stash, scnt);

    s_red[tid] = e0 + e1; __syncthreads();
    for (int off = 64; off > 0; off >>= 1) {
        if (tid < off) s_red[tid] += s_red[tid + off];
        __syncthreads();
    }
    if (tid == 0) {
        g_partial[b*16 + t] = s_red[0];
        __threadfence();
        int done = atomicAdd(&g_cnt[b], 1);
        if (done == 15) {   // last block of this molecule: deterministic fixed-order sum
            volatile float* gp = g_partial;
            float s = 0.f;
            #pragma unroll
            for (int q = 0; q < 16; q++) s += gp[b*16 + q];
            out[b] = 332.0636f * s;
        }
    }
}

extern "C" void kernel_launch(void* const* d_in, const int* in_sizes, int n_in,
                              void* d_out, int out_size) {
    const float* e_z     = (const float*)d_in[0];
    const float* charge  = (const float*)d_in[1];
    const float* xyz     = (const float*)d_in[2];
    const float* W_lin   = (const float*)d_in[3];
    const float* b_lin   = (const float*)d_in[4];
    const float* k_plus  = (const float*)d_in[5];
    const float* k_minus = (const float*)d_in[6];
    const float* v_plus  = (const float*)d_in[7];
    const float* v_minus = (const float*)d_in[8];
    const float* Wr1     = (const float*)d_in[9];
    const float* Wr2     = (const float*)d_in[10];
    const float* Wout    = (const float*)d_in[11];
    const float* w_e     = (const float*)d_in[12];
    const float* q_tab   = (const float*)d_in[13];
    const int*   z       = (const int*)d_in[14];
    float* out = (float*)d_out;

    cudaFuncSetAttribute(k2_mma, cudaFuncAttributeMaxDynamicSharedMemorySize, K2_SMEM);

    k0f<<<193, 256>>>(Wr1, Wr2, W_lin, b_lin, k_plus, k_minus, Wout, w_e);
    k1_fused<<<NN/256, 256>>>(e_z, charge, w_e);
    k2_mma<<<NN/128, 256, K2_SMEM>>>(charge, z, q_tab, v_plus, v_minus);
    dim3 g4(16, BB);
    k4_pair<<<g4, 128>>>(xyz, charge, out);
}